// round 14
// baseline (speedup 1.0000x reference)
#include <cuda_runtime.h>
#include <cuda_bf16.h>
#include <math.h>
#include <stdint.h>

#define N 8192
#define D 128
#define TILE 128
#define NT 256
#define T_PER 32                  // j-tiles per CTA (grid (64,2))

#define A_OFF 0
#define B_OFF(b) (TILE * D + (b) * TILE * D)     // floats
#define SMEM_BYTES (3 * TILE * D * 4)            // 196608 = 192KB

static __device__ __align__(16) float g_embR[N * D];  // tf32-rounded, k-group-permuted
static __device__ float g_sq[N];
static __device__ int   g_lab[N];
static __device__ int   g_pos[N];
static __device__ int   g_neg[N];
static __device__ float g_sum;

__device__ __forceinline__ void mma8(float* c, uint32_t a0, uint32_t a1, uint32_t a2,
                                     uint32_t a3, uint32_t b0, uint32_t b1) {
    asm volatile(
        "mma.sync.aligned.m16n8k8.row.col.f32.tf32.tf32.f32 "
        "{%0,%1,%2,%3},{%4,%5,%6,%7},{%8,%9},{%0,%1,%2,%3};"
        : "+f"(c[0]), "+f"(c[1]), "+f"(c[2]), "+f"(c[3])
        : "r"(a0), "r"(a1), "r"(a2), "r"(a3), "r"(b0), "r"(b1));
}
#define FU(x) __float_as_uint(x)

// ---------------------------------------------------------------------------
// 0) labels: handle int32 OR int64 buffer layout (probe odd words); zero g_sum
// ---------------------------------------------------------------------------
__global__ void k_labels(const int* __restrict__ lab32) {
    __shared__ int stride;
    if (threadIdx.x == 0) {
        int s = 2;
        for (int i = 1; i < 128; i += 2)
            if (lab32[i] != 0) { s = 1; break; }
        stride = s;
    }
    __syncthreads();
    int i = blockIdx.x * blockDim.x + threadIdx.x;
    if (i < N) g_lab[i] = lab32[i * stride];
    if (i == 0) g_sum = 0.0f;
}

// ---------------------------------------------------------------------------
// 1) prep: tf32-round; permute each 16-float k-group (new[4t+m] = old[t+4m]);
//    norms of rounded copy; init reductions
// ---------------------------------------------------------------------------
__global__ void k_prep(const float* __restrict__ emb) {
    int warp = threadIdx.x >> 5, lane = threadIdx.x & 31;
    int row = blockIdx.x * 8 + warp;
    int b = lane >> 2, t = lane & 3;
    const float* src = emb + (size_t)row * D + b * 16 + t;
    float4 r;
    asm("cvt.rna.tf32.f32 %0, %1;" : "=f"(r.x) : "f"(src[0]));
    asm("cvt.rna.tf32.f32 %0, %1;" : "=f"(r.y) : "f"(src[4]));
    asm("cvt.rna.tf32.f32 %0, %1;" : "=f"(r.z) : "f"(src[8]));
    asm("cvt.rna.tf32.f32 %0, %1;" : "=f"(r.w) : "f"(src[12]));
    float s = r.x * r.x + r.y * r.y + r.z * r.z + r.w * r.w;
#pragma unroll
    for (int o = 16; o > 0; o >>= 1) s += __shfl_xor_sync(0xffffffffu, s, o);
    *(float4*)(g_embR + (size_t)row * D + b * 16 + 4 * t) = r;
    if (lane == 0) {
        g_sq[row]  = s;
        g_pos[row] = 0;
        g_neg[row] = 0x7f800000;
    }
}

// ---------------------------------------------------------------------------
// 2) main: mma.sync tf32 d^2-GEMM + fused pos/neg reduction
//    grid (64, 2): x = i-tile, y = j-half; A tile resident for 32 j-tiles.
//    SMEM layout: row-major 128 floats/row, 16B-chunk index XOR'd with
//    (row&1)*4  ->  all LDS.128 phases conflict-free.
// ---------------------------------------------------------------------------
__global__ void __launch_bounds__(NT) k_main() {
    extern __shared__ float smem[];
    const int tid  = threadIdx.x;
    const int wid  = tid >> 5;
    const int lane = tid & 31;
    const int wm   = wid & 3;
    const int wn   = wid >> 2;
    const int g    = lane >> 2;
    const int tg   = lane & 3;
    const int xk   = g & 1;                 // kb XOR (row-parity swizzle, see header)
    const int i0    = blockIdx.x * TILE;
    const int jbase = blockIdx.y * T_PER * TILE;

    // ---- prologue: A tile + B(0) via cp.async with swizzled chunk index ----
#pragma unroll
    for (int q = 0; q < 16; q++) {
        int idx = q * NT + tid;
        int row = idx >> 5, ch = idx & 31;
        int chs = ch ^ ((row & 1) * 4);     // swizzled 16B-chunk
        uint32_t dstA = (uint32_t)__cvta_generic_to_shared(&smem[A_OFF + row * D + chs * 4]);
        uint32_t dstB = (uint32_t)__cvta_generic_to_shared(&smem[B_OFF(0) + row * D + chs * 4]);
        const float* srcA = g_embR + (size_t)(i0 + row) * D + ch * 4;
        const float* srcB = g_embR + (size_t)(jbase + row) * D + ch * 4;
        asm volatile("cp.async.cg.shared.global [%0], [%1], 16;" :: "r"(dstA), "l"(srcA));
        asm volatile("cp.async.cg.shared.global [%0], [%1], 16;" :: "r"(dstB), "l"(srcB));
    }
    asm volatile("cp.async.commit_group;");

    // ---- per-thread row metadata ----
    float sI[4]; int lI[4]; float pm[4], nm[4];
#pragma unroll
    for (int ridx = 0; ridx < 4; ridx++) {
        int row = i0 + wm * 32 + (ridx >> 1) * 16 + (ridx & 1) * 8 + g;
        sI[ridx] = g_sq[row];
        lI[ridx] = g_lab[row];
        pm[ridx] = 0.0f;
        nm[ridx] = __int_as_float(0x7f800000);
    }

    for (int tt = 0; tt < T_PER; tt++) {
        if (tt + 1 < T_PER) {
            const int nb = (tt + 1) & 1;
#pragma unroll
            for (int q = 0; q < 16; q++) {
                int idx = q * NT + tid;
                int row = idx >> 5, ch = idx & 31;
                int chs = ch ^ ((row & 1) * 4);
                uint32_t dst = (uint32_t)__cvta_generic_to_shared(&smem[B_OFF(nb) + row * D + chs * 4]);
                const float* src = g_embR + (size_t)(jbase + (tt + 1) * TILE + row) * D + ch * 4;
                asm volatile("cp.async.cg.shared.global [%0], [%1], 16;" :: "r"(dst), "l"(src));
            }
            asm volatile("cp.async.commit_group;");
            asm volatile("cp.async.wait_group 1;" ::: "memory");
        } else {
            asm volatile("cp.async.wait_group 0;" ::: "memory");
        }
        __syncthreads();   // B(tt) visible

        float acc[2][8][4];
#pragma unroll
        for (int mt = 0; mt < 2; mt++)
#pragma unroll
            for (int nt = 0; nt < 8; nt++)
#pragma unroll
                for (int c = 0; c < 4; c++) acc[mt][nt][c] = 0.0f;

        const float* Au = smem + A_OFF;
        const float* Bu = smem + B_OFF(tt & 1);
        const int ar0 = (wm * 32 + g) * D;
        const int ar1 = ar0 + 8 * D;
        const int ar2 = ar0 + 16 * D;
        const int ar3 = ar0 + 24 * D;
        const int brow = (wn * 64 + g) * D;

#pragma unroll
        for (int kb = 0; kb < 8; kb++) {
            const int off = (kb ^ xk) * 16 + 4 * tg;   // swizzled load offset
            float4 a00 = *(const float4*)(Au + ar0 + off);
            float4 a01 = *(const float4*)(Au + ar1 + off);
            float4 a10 = *(const float4*)(Au + ar2 + off);
            float4 a11 = *(const float4*)(Au + ar3 + off);
            float4 bb[8];
#pragma unroll
            for (int nt = 0; nt < 8; nt++)
                bb[nt] = *(const float4*)(Bu + brow + nt * 8 * D + off);
#pragma unroll
            for (int nt = 0; nt < 8; nt++) {
                mma8(acc[0][nt], FU(a00.x), FU(a01.x), FU(a00.y), FU(a01.y),
                     FU(bb[nt].x), FU(bb[nt].y));
                mma8(acc[1][nt], FU(a10.x), FU(a11.x), FU(a10.y), FU(a11.y),
                     FU(bb[nt].x), FU(bb[nt].y));
                mma8(acc[0][nt], FU(a00.z), FU(a01.z), FU(a00.w), FU(a01.w),
                     FU(bb[nt].z), FU(bb[nt].w));
                mma8(acc[1][nt], FU(a10.z), FU(a11.z), FU(a10.w), FU(a11.w),
                     FU(bb[nt].z), FU(bb[nt].w));
            }
        }
        __syncthreads();   // compute(tt) done; buffer may be refilled

        // ---- epilogue: d^2 + pos/neg reduction ----
        float sj[16]; int lj[16];
#pragma unroll
        for (int nt = 0; nt < 8; nt++)
#pragma unroll
            for (int u = 0; u < 2; u++) {
                int j = jbase + tt * TILE + wn * 64 + nt * 8 + 2 * tg + u;
                sj[nt * 2 + u] = g_sq[j];
                lj[nt * 2 + u] = g_lab[j];
            }
#pragma unroll
        for (int mt = 0; mt < 2; mt++)
#pragma unroll
            for (int h = 0; h < 2; h++) {
                const int ridx = mt * 2 + h;
                float si = sI[ridx];
                int   li = lI[ridx];
                float p = pm[ridx], n = nm[ridx];
#pragma unroll
                for (int nt = 0; nt < 8; nt++)
#pragma unroll
                    for (int u = 0; u < 2; u++) {
                        float d2 = fmaf(-2.0f, acc[mt][nt][h * 2 + u], si + sj[nt * 2 + u]);
                        d2 = fmaxf(d2, 0.0f);
                        if (li == lj[nt * 2 + u]) p = fmaxf(p, d2);
                        else                      n = fminf(n, d2);
                    }
                pm[ridx] = p; nm[ridx] = n;
            }
    }

    // ---- merge partial reductions ----
#pragma unroll
    for (int ridx = 0; ridx < 4; ridx++) {
        float p = pm[ridx], n = nm[ridx];
        p = fmaxf(p, __shfl_xor_sync(0xffffffffu, p, 1));
        p = fmaxf(p, __shfl_xor_sync(0xffffffffu, p, 2));
        n = fminf(n, __shfl_xor_sync(0xffffffffu, n, 1));
        n = fminf(n, __shfl_xor_sync(0xffffffffu, n, 2));
        if (tg == 0) {
            int row = i0 + wm * 32 + (ridx >> 1) * 16 + (ridx & 1) * 8 + g;
            atomicMax(&g_pos[row], __float_as_int(p));
            atomicMin(&g_neg[row], __float_as_int(n));
        }
    }
}

// ---------------------------------------------------------------------------
// 3) finalize: parallel sum of relu(sqrt(pos)-sqrt(neg)+margin), then divide
// ---------------------------------------------------------------------------
__global__ void k_final1(const float* __restrict__ margin) {
    int i = blockIdx.x * 1024 + threadIdx.x;
    float m = *margin;
    float p = sqrtf(__int_as_float(g_pos[i]));
    float n = sqrtf(__int_as_float(g_neg[i]));
    float v = fmaxf(p - n + m, 0.0f);
#pragma unroll
    for (int o = 16; o > 0; o >>= 1) v += __shfl_xor_sync(0xffffffffu, v, o);
    __shared__ float red[32];
    int wid = threadIdx.x >> 5, lane = threadIdx.x & 31;
    if (lane == 0) red[wid] = v;
    __syncthreads();
    if (wid == 0) {
        float s = red[lane];
#pragma unroll
        for (int o = 16; o > 0; o >>= 1) s += __shfl_xor_sync(0xffffffffu, s, o);
        if (lane == 0) atomicAdd(&g_sum, s);
    }
}
__global__ void k_final2(float* __restrict__ out) { out[0] = g_sum / (float)N; }

// ---------------------------------------------------------------------------
extern "C" void kernel_launch(void* const* d_in, const int* in_sizes, int n_in,
                              void* d_out, int out_size) {
    const float* emb    = (const float*)d_in[0];
    const int*   lab32  = (const int*)d_in[1];
    const float* margin = (const float*)d_in[2];
    float*       out    = (float*)d_out;

    cudaFuncSetAttribute(k_main, cudaFuncAttributeMaxDynamicSharedMemorySize, SMEM_BYTES);

    k_labels<<<N / 256, 256>>>(lab32);
    k_prep<<<N / 8, 256>>>(emb);
    k_main<<<dim3(N / TILE, 2), NT, SMEM_BYTES>>>();
    k_final1<<<N / 1024, 1024>>>(margin);
    k_final2<<<1, 1>>>(out);
}

// round 15
// speedup vs baseline: 1.0006x; 1.0006x over previous
#include <cuda_runtime.h>
#include <cuda_bf16.h>
#include <math.h>
#include <stdint.h>

#define N 8192
#define D 128
#define TILE 128
#define NT 256
#define T_PER 32                  // j-tiles per CTA (grid (64,2))

#define A_OFF 0
#define B_OFF(b) (TILE * D + (b) * TILE * D)     // floats
#define SMEM_BYTES (3 * TILE * D * 4)            // 196608 = 192KB

static __device__ __align__(16) float g_embR[N * D];  // tf32-rounded, k-group-permuted
static __device__ float g_sq[N];
static __device__ int   g_lab[N];
static __device__ int   g_pos[N];
static __device__ int   g_neg[N];
static __device__ float g_sum;

__device__ __forceinline__ void mma8(float* c, uint32_t a0, uint32_t a1, uint32_t a2,
                                     uint32_t a3, uint32_t b0, uint32_t b1) {
    asm volatile(
        "mma.sync.aligned.m16n8k8.row.col.f32.tf32.tf32.f32 "
        "{%0,%1,%2,%3},{%4,%5,%6,%7},{%8,%9},{%0,%1,%2,%3};"
        : "+f"(c[0]), "+f"(c[1]), "+f"(c[2]), "+f"(c[3])
        : "r"(a0), "r"(a1), "r"(a2), "r"(a3), "r"(b0), "r"(b1));
}
#define FU(x) __float_as_uint(x)

// ---------------------------------------------------------------------------
// 0) labels: handle int32 OR int64 buffer layout (probe odd words); zero g_sum
// ---------------------------------------------------------------------------
__global__ void k_labels(const int* __restrict__ lab32) {
    __shared__ int stride;
    if (threadIdx.x == 0) {
        int s = 2;
        for (int i = 1; i < 128; i += 2)
            if (lab32[i] != 0) { s = 1; break; }
        stride = s;
    }
    __syncthreads();
    int i = blockIdx.x * blockDim.x + threadIdx.x;
    if (i < N) g_lab[i] = lab32[i * stride];
    if (i == 0) g_sum = 0.0f;
}

// ---------------------------------------------------------------------------
// 1) prep: tf32-round; permute each 16-float k-group (new[4t+m] = old[t+4m]);
//    norms of rounded copy; init reductions
// ---------------------------------------------------------------------------
__global__ void k_prep(const float* __restrict__ emb) {
    int warp = threadIdx.x >> 5, lane = threadIdx.x & 31;
    int row = blockIdx.x * 8 + warp;
    int b = lane >> 2, t = lane & 3;
    const float* src = emb + (size_t)row * D + b * 16 + t;
    float4 r;
    asm("cvt.rna.tf32.f32 %0, %1;" : "=f"(r.x) : "f"(src[0]));
    asm("cvt.rna.tf32.f32 %0, %1;" : "=f"(r.y) : "f"(src[4]));
    asm("cvt.rna.tf32.f32 %0, %1;" : "=f"(r.z) : "f"(src[8]));
    asm("cvt.rna.tf32.f32 %0, %1;" : "=f"(r.w) : "f"(src[12]));
    float s = r.x * r.x + r.y * r.y + r.z * r.z + r.w * r.w;
#pragma unroll
    for (int o = 16; o > 0; o >>= 1) s += __shfl_xor_sync(0xffffffffu, s, o);
    *(float4*)(g_embR + (size_t)row * D + b * 16 + 4 * t) = r;
    if (lane == 0) {
        g_sq[row]  = s;
        g_pos[row] = 0;
        g_neg[row] = 0x7f800000;
    }
}

// ---------------------------------------------------------------------------
// 2) main: mma.sync tf32 d^2-GEMM + fused pos/neg reduction
//    grid (64, 2): x = i-tile, y = j-half; A tile resident for 32 j-tiles.
//    SMEM layout: row-major 128 floats/row, 16B-chunk index XOR'd with
//    (row&1)*4  ->  all LDS.128 phases conflict-free.
// ---------------------------------------------------------------------------
__global__ void __launch_bounds__(NT) k_main() {
    extern __shared__ float smem[];
    const int tid  = threadIdx.x;
    const int wid  = tid >> 5;
    const int lane = tid & 31;
    const int wm   = wid & 3;
    const int wn   = wid >> 2;
    const int g    = lane >> 2;
    const int tg   = lane & 3;
    const int xk   = g & 1;                 // kb XOR (row-parity swizzle, see header)
    const int i0    = blockIdx.x * TILE;
    const int jbase = blockIdx.y * T_PER * TILE;

    // ---- prologue: A tile + B(0) via cp.async with swizzled chunk index ----
#pragma unroll
    for (int q = 0; q < 16; q++) {
        int idx = q * NT + tid;
        int row = idx >> 5, ch = idx & 31;
        int chs = ch ^ ((row & 1) * 4);     // swizzled 16B-chunk
        uint32_t dstA = (uint32_t)__cvta_generic_to_shared(&smem[A_OFF + row * D + chs * 4]);
        uint32_t dstB = (uint32_t)__cvta_generic_to_shared(&smem[B_OFF(0) + row * D + chs * 4]);
        const float* srcA = g_embR + (size_t)(i0 + row) * D + ch * 4;
        const float* srcB = g_embR + (size_t)(jbase + row) * D + ch * 4;
        asm volatile("cp.async.cg.shared.global [%0], [%1], 16;" :: "r"(dstA), "l"(srcA));
        asm volatile("cp.async.cg.shared.global [%0], [%1], 16;" :: "r"(dstB), "l"(srcB));
    }
    asm volatile("cp.async.commit_group;");

    // ---- per-thread row metadata ----
    float sI[4]; int lI[4]; float pm[4], nm[4];
#pragma unroll
    for (int ridx = 0; ridx < 4; ridx++) {
        int row = i0 + wm * 32 + (ridx >> 1) * 16 + (ridx & 1) * 8 + g;
        sI[ridx] = g_sq[row];
        lI[ridx] = g_lab[row];
        pm[ridx] = 0.0f;
        nm[ridx] = __int_as_float(0x7f800000);
    }

    for (int tt = 0; tt < T_PER; tt++) {
        if (tt + 1 < T_PER) {
            const int nb = (tt + 1) & 1;
#pragma unroll
            for (int q = 0; q < 16; q++) {
                int idx = q * NT + tid;
                int row = idx >> 5, ch = idx & 31;
                int chs = ch ^ ((row & 1) * 4);
                uint32_t dst = (uint32_t)__cvta_generic_to_shared(&smem[B_OFF(nb) + row * D + chs * 4]);
                const float* src = g_embR + (size_t)(jbase + (tt + 1) * TILE + row) * D + ch * 4;
                asm volatile("cp.async.cg.shared.global [%0], [%1], 16;" :: "r"(dst), "l"(src));
            }
            asm volatile("cp.async.commit_group;");
            asm volatile("cp.async.wait_group 1;" ::: "memory");
        } else {
            asm volatile("cp.async.wait_group 0;" ::: "memory");
        }
        __syncthreads();   // B(tt) visible

        float acc[2][8][4];
#pragma unroll
        for (int mt = 0; mt < 2; mt++)
#pragma unroll
            for (int nt = 0; nt < 8; nt++)
#pragma unroll
                for (int c = 0; c < 4; c++) acc[mt][nt][c] = 0.0f;

        const float* Au = smem + A_OFF;
        const float* Bu = smem + B_OFF(tt & 1);
        const int ar0 = (wm * 32 + g) * D;
        const int ar1 = ar0 + 8 * D;
        const int ar2 = ar0 + 16 * D;
        const int ar3 = ar0 + 24 * D;
        const int brow = (wn * 64 + g) * D;

#pragma unroll
        for (int kb = 0; kb < 8; kb++) {
            const int off = (kb ^ xk) * 16 + 4 * tg;   // swizzled load offset
            float4 a00 = *(const float4*)(Au + ar0 + off);
            float4 a01 = *(const float4*)(Au + ar1 + off);
            float4 a10 = *(const float4*)(Au + ar2 + off);
            float4 a11 = *(const float4*)(Au + ar3 + off);
            float4 bb[8];
#pragma unroll
            for (int nt = 0; nt < 8; nt++)
                bb[nt] = *(const float4*)(Bu + brow + nt * 8 * D + off);
#pragma unroll
            for (int nt = 0; nt < 8; nt++) {
                mma8(acc[0][nt], FU(a00.x), FU(a01.x), FU(a00.y), FU(a01.y),
                     FU(bb[nt].x), FU(bb[nt].y));
                mma8(acc[1][nt], FU(a10.x), FU(a11.x), FU(a10.y), FU(a11.y),
                     FU(bb[nt].x), FU(bb[nt].y));
                mma8(acc[0][nt], FU(a00.z), FU(a01.z), FU(a00.w), FU(a01.w),
                     FU(bb[nt].z), FU(bb[nt].w));
                mma8(acc[1][nt], FU(a10.z), FU(a11.z), FU(a10.w), FU(a11.w),
                     FU(bb[nt].z), FU(bb[nt].w));
            }
        }
        __syncthreads();   // compute(tt) done; buffer may be refilled

        // ---- epilogue: d^2 + pos/neg reduction ----
        float sj[16]; int lj[16];
#pragma unroll
        for (int nt = 0; nt < 8; nt++)
#pragma unroll
            for (int u = 0; u < 2; u++) {
                int j = jbase + tt * TILE + wn * 64 + nt * 8 + 2 * tg + u;
                sj[nt * 2 + u] = g_sq[j];
                lj[nt * 2 + u] = g_lab[j];
            }
#pragma unroll
        for (int mt = 0; mt < 2; mt++)
#pragma unroll
            for (int h = 0; h < 2; h++) {
                const int ridx = mt * 2 + h;
                float si = sI[ridx];
                int   li = lI[ridx];
                float p = pm[ridx], n = nm[ridx];
#pragma unroll
                for (int nt = 0; nt < 8; nt++)
#pragma unroll
                    for (int u = 0; u < 2; u++) {
                        float d2 = fmaf(-2.0f, acc[mt][nt][h * 2 + u], si + sj[nt * 2 + u]);
                        d2 = fmaxf(d2, 0.0f);
                        if (li == lj[nt * 2 + u]) p = fmaxf(p, d2);
                        else                      n = fminf(n, d2);
                    }
                pm[ridx] = p; nm[ridx] = n;
            }
    }

    // ---- merge partial reductions ----
#pragma unroll
    for (int ridx = 0; ridx < 4; ridx++) {
        float p = pm[ridx], n = nm[ridx];
        p = fmaxf(p, __shfl_xor_sync(0xffffffffu, p, 1));
        p = fmaxf(p, __shfl_xor_sync(0xffffffffu, p, 2));
        n = fminf(n, __shfl_xor_sync(0xffffffffu, n, 1));
        n = fminf(n, __shfl_xor_sync(0xffffffffu, n, 2));
        if (tg == 0) {
            int row = i0 + wm * 32 + (ridx >> 1) * 16 + (ridx & 1) * 8 + g;
            atomicMax(&g_pos[row], __float_as_int(p));
            atomicMin(&g_neg[row], __float_as_int(n));
        }
    }
}

// ---------------------------------------------------------------------------
// 3) finalize: parallel sum of relu(sqrt(pos)-sqrt(neg)+margin), then divide
// ---------------------------------------------------------------------------
__global__ void k_final1(const float* __restrict__ margin) {
    int i = blockIdx.x * 1024 + threadIdx.x;
    float m = *margin;
    float p = sqrtf(__int_as_float(g_pos[i]));
    float n = sqrtf(__int_as_float(g_neg[i]));
    float v = fmaxf(p - n + m, 0.0f);
#pragma unroll
    for (int o = 16; o > 0; o >>= 1) v += __shfl_xor_sync(0xffffffffu, v, o);
    __shared__ float red[32];
    int wid = threadIdx.x >> 5, lane = threadIdx.x & 31;
    if (lane == 0) red[wid] = v;
    __syncthreads();
    if (wid == 0) {
        float s = red[lane];
#pragma unroll
        for (int o = 16; o > 0; o >>= 1) s += __shfl_xor_sync(0xffffffffu, s, o);
        if (lane == 0) atomicAdd(&g_sum, s);
    }
}
__global__ void k_final2(float* __restrict__ out) { out[0] = g_sum / (float)N; }

// ---------------------------------------------------------------------------
extern "C" void kernel_launch(void* const* d_in, const int* in_sizes, int n_in,
                              void* d_out, int out_size) {
    const float* emb    = (const float*)d_in[0];
    const int*   lab32  = (const int*)d_in[1];
    const float* margin = (const float*)d_in[2];
    float*       out    = (float*)d_out;

    cudaFuncSetAttribute(k_main, cudaFuncAttributeMaxDynamicSharedMemorySize, SMEM_BYTES);

    k_labels<<<N / 256, 256>>>(lab32);
    k_prep<<<N / 8, 256>>>(emb);
    k_main<<<dim3(N / TILE, 2), NT, SMEM_BYTES>>>();
    k_final1<<<N / 1024, 1024>>>(margin);
    k_final2<<<1, 1>>>(out);
}

// round 16
// speedup vs baseline: 1.0050x; 1.0043x over previous
#include <cuda_runtime.h>
#include <cuda_bf16.h>
#include <math.h>
#include <stdint.h>

#define N 8192
#define D 128
#define TILE 128
#define NT 256
#define T_PER 32                  // j-tiles per CTA (grid (64,2))

#define A_OFF 0
#define B_OFF(b) (TILE * D + (b) * TILE * D)     // floats
#define SMEM_BYTES (3 * TILE * D * 4)            // 196608 = 192KB

static __device__ __align__(16) float g_embR[N * D];  // tf32-rounded, k-group-permuted
static __device__ float g_sq[N];
static __device__ int   g_lab[N];
static __device__ int   g_pos[N];
static __device__ int   g_neg[N];
static __device__ float g_sum;

__device__ __forceinline__ void mma8(float* c, uint32_t a0, uint32_t a1, uint32_t a2,
                                     uint32_t a3, uint32_t b0, uint32_t b1) {
    asm volatile(
        "mma.sync.aligned.m16n8k8.row.col.f32.tf32.tf32.f32 "
        "{%0,%1,%2,%3},{%4,%5,%6,%7},{%8,%9},{%0,%1,%2,%3};"
        : "+f"(c[0]), "+f"(c[1]), "+f"(c[2]), "+f"(c[3])
        : "r"(a0), "r"(a1), "r"(a2), "r"(a3), "r"(b0), "r"(b1));
}
#define FU(x) __float_as_uint(x)

// ---------------------------------------------------------------------------
// 0) labels: handle int32 OR int64 buffer layout (probe odd words); zero g_sum
// ---------------------------------------------------------------------------
__global__ void k_labels(const int* __restrict__ lab32) {
    __shared__ int stride;
    if (threadIdx.x == 0) {
        int s = 2;
        for (int i = 1; i < 128; i += 2)
            if (lab32[i] != 0) { s = 1; break; }
        stride = s;
    }
    __syncthreads();
    int i = blockIdx.x * blockDim.x + threadIdx.x;
    if (i < N) g_lab[i] = lab32[i * stride];
    if (i == 0) g_sum = 0.0f;
}

// ---------------------------------------------------------------------------
// 1) prep: tf32-round; permute each 16-float k-group (new[4t+m] = old[t+4m]);
//    norms of rounded copy; init reductions
// ---------------------------------------------------------------------------
__global__ void k_prep(const float* __restrict__ emb) {
    int warp = threadIdx.x >> 5, lane = threadIdx.x & 31;
    int row = blockIdx.x * 8 + warp;
    int b = lane >> 2, t = lane & 3;
    const float* src = emb + (size_t)row * D + b * 16 + t;
    float4 r;
    asm("cvt.rna.tf32.f32 %0, %1;" : "=f"(r.x) : "f"(src[0]));
    asm("cvt.rna.tf32.f32 %0, %1;" : "=f"(r.y) : "f"(src[4]));
    asm("cvt.rna.tf32.f32 %0, %1;" : "=f"(r.z) : "f"(src[8]));
    asm("cvt.rna.tf32.f32 %0, %1;" : "=f"(r.w) : "f"(src[12]));
    float s = r.x * r.x + r.y * r.y + r.z * r.z + r.w * r.w;
#pragma unroll
    for (int o = 16; o > 0; o >>= 1) s += __shfl_xor_sync(0xffffffffu, s, o);
    *(float4*)(g_embR + (size_t)row * D + b * 16 + 4 * t) = r;
    if (lane == 0) {
        g_sq[row]  = s;
        g_pos[row] = 0;
        g_neg[row] = 0x7f800000;
    }
}

// ---------------------------------------------------------------------------
// 2) main: mma.sync tf32 d^2-GEMM + fused pos/neg reduction
//    grid (64, 2): x = i-tile, y = j-half; A tile resident for 32 j-tiles.
//    SMEM layout: row-major 128 floats/row, 16B-chunk index XOR'd with
//    (row&1)*4  ->  all LDS.128 phases conflict-free.
// ---------------------------------------------------------------------------
__global__ void __launch_bounds__(NT) k_main() {
    extern __shared__ float smem[];
    const int tid  = threadIdx.x;
    const int wid  = tid >> 5;
    const int lane = tid & 31;
    const int wm   = wid & 3;
    const int wn   = wid >> 2;
    const int g    = lane >> 2;
    const int tg   = lane & 3;
    const int xk   = g & 1;                 // kb XOR (row-parity swizzle, see header)
    const int i0    = blockIdx.x * TILE;
    const int jbase = blockIdx.y * T_PER * TILE;

    // ---- prologue: A tile + B(0) via cp.async with swizzled chunk index ----
#pragma unroll
    for (int q = 0; q < 16; q++) {
        int idx = q * NT + tid;
        int row = idx >> 5, ch = idx & 31;
        int chs = ch ^ ((row & 1) * 4);     // swizzled 16B-chunk
        uint32_t dstA = (uint32_t)__cvta_generic_to_shared(&smem[A_OFF + row * D + chs * 4]);
        uint32_t dstB = (uint32_t)__cvta_generic_to_shared(&smem[B_OFF(0) + row * D + chs * 4]);
        const float* srcA = g_embR + (size_t)(i0 + row) * D + ch * 4;
        const float* srcB = g_embR + (size_t)(jbase + row) * D + ch * 4;
        asm volatile("cp.async.cg.shared.global [%0], [%1], 16;" :: "r"(dstA), "l"(srcA));
        asm volatile("cp.async.cg.shared.global [%0], [%1], 16;" :: "r"(dstB), "l"(srcB));
    }
    asm volatile("cp.async.commit_group;");

    // ---- per-thread row metadata ----
    float sI[4]; int lI[4]; float pm[4], nm[4];
#pragma unroll
    for (int ridx = 0; ridx < 4; ridx++) {
        int row = i0 + wm * 32 + (ridx >> 1) * 16 + (ridx & 1) * 8 + g;
        sI[ridx] = g_sq[row];
        lI[ridx] = g_lab[row];
        pm[ridx] = 0.0f;
        nm[ridx] = __int_as_float(0x7f800000);
    }

    for (int tt = 0; tt < T_PER; tt++) {
        if (tt + 1 < T_PER) {
            const int nb = (tt + 1) & 1;
#pragma unroll
            for (int q = 0; q < 16; q++) {
                int idx = q * NT + tid;
                int row = idx >> 5, ch = idx & 31;
                int chs = ch ^ ((row & 1) * 4);
                uint32_t dst = (uint32_t)__cvta_generic_to_shared(&smem[B_OFF(nb) + row * D + chs * 4]);
                const float* src = g_embR + (size_t)(jbase + (tt + 1) * TILE + row) * D + ch * 4;
                asm volatile("cp.async.cg.shared.global [%0], [%1], 16;" :: "r"(dst), "l"(src));
            }
            asm volatile("cp.async.commit_group;");
            asm volatile("cp.async.wait_group 1;" ::: "memory");
        } else {
            asm volatile("cp.async.wait_group 0;" ::: "memory");
        }
        __syncthreads();   // B(tt) visible

        float acc[2][8][4];
#pragma unroll
        for (int mt = 0; mt < 2; mt++)
#pragma unroll
            for (int nt = 0; nt < 8; nt++)
#pragma unroll
                for (int c = 0; c < 4; c++) acc[mt][nt][c] = 0.0f;

        const float* Au = smem + A_OFF;
        const float* Bu = smem + B_OFF(tt & 1);
        const int ar0 = (wm * 32 + g) * D;
        const int ar1 = ar0 + 8 * D;
        const int ar2 = ar0 + 16 * D;
        const int ar3 = ar0 + 24 * D;
        const int brow = (wn * 64 + g) * D;

#pragma unroll
        for (int kb = 0; kb < 8; kb++) {
            const int off = (kb ^ xk) * 16 + 4 * tg;   // swizzled load offset
            float4 a00 = *(const float4*)(Au + ar0 + off);
            float4 a01 = *(const float4*)(Au + ar1 + off);
            float4 a10 = *(const float4*)(Au + ar2 + off);
            float4 a11 = *(const float4*)(Au + ar3 + off);
            float4 bb[8];
#pragma unroll
            for (int nt = 0; nt < 8; nt++)
                bb[nt] = *(const float4*)(Bu + brow + nt * 8 * D + off);
#pragma unroll
            for (int nt = 0; nt < 8; nt++) {
                mma8(acc[0][nt], FU(a00.x), FU(a01.x), FU(a00.y), FU(a01.y),
                     FU(bb[nt].x), FU(bb[nt].y));
                mma8(acc[1][nt], FU(a10.x), FU(a11.x), FU(a10.y), FU(a11.y),
                     FU(bb[nt].x), FU(bb[nt].y));
                mma8(acc[0][nt], FU(a00.z), FU(a01.z), FU(a00.w), FU(a01.w),
                     FU(bb[nt].z), FU(bb[nt].w));
                mma8(acc[1][nt], FU(a10.z), FU(a11.z), FU(a10.w), FU(a11.w),
                     FU(bb[nt].z), FU(bb[nt].w));
            }
        }
        __syncthreads();   // compute(tt) done; buffer may be refilled

        // ---- epilogue: d^2 + pos/neg reduction ----
        float sj[16]; int lj[16];
#pragma unroll
        for (int nt = 0; nt < 8; nt++)
#pragma unroll
            for (int u = 0; u < 2; u++) {
                int j = jbase + tt * TILE + wn * 64 + nt * 8 + 2 * tg + u;
                sj[nt * 2 + u] = g_sq[j];
                lj[nt * 2 + u] = g_lab[j];
            }
#pragma unroll
        for (int mt = 0; mt < 2; mt++)
#pragma unroll
            for (int h = 0; h < 2; h++) {
                const int ridx = mt * 2 + h;
                float si = sI[ridx];
                int   li = lI[ridx];
                float p = pm[ridx], n = nm[ridx];
#pragma unroll
                for (int nt = 0; nt < 8; nt++)
#pragma unroll
                    for (int u = 0; u < 2; u++) {
                        float d2 = fmaf(-2.0f, acc[mt][nt][h * 2 + u], si + sj[nt * 2 + u]);
                        d2 = fmaxf(d2, 0.0f);
                        if (li == lj[nt * 2 + u]) p = fmaxf(p, d2);
                        else                      n = fminf(n, d2);
                    }
                pm[ridx] = p; nm[ridx] = n;
            }
    }

    // ---- merge partial reductions ----
#pragma unroll
    for (int ridx = 0; ridx < 4; ridx++) {
        float p = pm[ridx], n = nm[ridx];
        p = fmaxf(p, __shfl_xor_sync(0xffffffffu, p, 1));
        p = fmaxf(p, __shfl_xor_sync(0xffffffffu, p, 2));
        n = fminf(n, __shfl_xor_sync(0xffffffffu, n, 1));
        n = fminf(n, __shfl_xor_sync(0xffffffffu, n, 2));
        if (tg == 0) {
            int row = i0 + wm * 32 + (ridx >> 1) * 16 + (ridx & 1) * 8 + g;
            atomicMax(&g_pos[row], __float_as_int(p));
            atomicMin(&g_neg[row], __float_as_int(n));
        }
    }
}

// ---------------------------------------------------------------------------
// 3) finalize: parallel sum of relu(sqrt(pos)-sqrt(neg)+margin), then divide
// ---------------------------------------------------------------------------
__global__ void k_final1(const float* __restrict__ margin) {
    int i = blockIdx.x * 1024 + threadIdx.x;
    float m = *margin;
    float p = sqrtf(__int_as_float(g_pos[i]));
    float n = sqrtf(__int_as_float(g_neg[i]));
    float v = fmaxf(p - n + m, 0.0f);
#pragma unroll
    for (int o = 16; o > 0; o >>= 1) v += __shfl_xor_sync(0xffffffffu, v, o);
    __shared__ float red[32];
    int wid = threadIdx.x >> 5, lane = threadIdx.x & 31;
    if (lane == 0) red[wid] = v;
    __syncthreads();
    if (wid == 0) {
        float s = red[lane];
#pragma unroll
        for (int o = 16; o > 0; o >>= 1) s += __shfl_xor_sync(0xffffffffu, s, o);
        if (lane == 0) atomicAdd(&g_sum, s);
    }
}
__global__ void k_final2(float* __restrict__ out) { out[0] = g_sum / (float)N; }

// ---------------------------------------------------------------------------
extern "C" void kernel_launch(void* const* d_in, const int* in_sizes, int n_in,
                              void* d_out, int out_size) {
    const float* emb    = (const float*)d_in[0];
    const int*   lab32  = (const int*)d_in[1];
    const float* margin = (const float*)d_in[2];
    float*       out    = (float*)d_out;

    cudaFuncSetAttribute(k_main, cudaFuncAttributeMaxDynamicSharedMemorySize, SMEM_BYTES);

    k_labels<<<N / 256, 256>>>(lab32);
    k_prep<<<N / 8, 256>>>(emb);
    k_main<<<dim3(N / TILE, 2), NT, SMEM_BYTES>>>();
    k_final1<<<N / 1024, 1024>>>(margin);
    k_final2<<<1, 1>>>(out);
}